// round 6
// baseline (speedup 1.0000x reference)
#include <cuda_runtime.h>
#include <cuda_fp16.h>
#include <math.h>
#include <stdint.h>

// ---------------------------------------------------------------------------
// Problem constants
// ---------------------------------------------------------------------------
constexpr int T_     = 1024;
constexpr int B_     = 64;
constexpr int NINP   = 800;
constexpr int NHID   = 1200;
constexpr int NSLOTS = 15;

constexpr int Msz   = T_ * B_;     // 65536 rows (m = t*64 + b)
constexpr int Ksz   = 2 * NINP;    // 1600
constexpr int NP    = 1280;        // NHID padded
constexpr int Erows = Msz + B_;    // 65600 rows of emb_full flattened [t][b]

constexpr int BM = 256, BN = 128, BK = 64;
constexpr int NSTG  = Ksz / BK;    // 25
constexpr int NT    = NP / BN;     // 10
constexpr int MT    = Msz / BM;    // 256
constexpr int NSLOT = NT * 2;      // 20 partial slots

// Output layout
constexpr size_t OFF_MG   = 0;
constexpr size_t OFF_MGN  = (size_t)B_ * T_ * NSLOTS;
constexpr size_t OFF_GATE = OFF_MGN + (size_t)B_ * T_ * NSLOTS;
constexpr size_t OFF_DIST = OFF_GATE + (size_t)B_ * T_;
constexpr size_t OFF_EMB  = OFF_DIST + (size_t)B_ * T_;
constexpr size_t OFF_CUM  = OFF_EMB + (size_t)B_ * NINP;

// Scratch (device globals)
__device__ __half g_E[(size_t)Erows * NINP];    // 105 MB  fp16 emb_full
__device__ __half g_W[(size_t)NP * Ksz];        // 4.1 MB  [n][k], BN folded, fp16
__device__ float g_rw[4 * NP];                  // wg0, wg1, wd, bias
__device__ float g_part[3 * NSLOT * Msz];       // epilogue partials, bt-major

__device__ __forceinline__ float sigmf(float x) { return 1.f / (1.f + expf(-x)); }

// ---------------------------------------------------------------------------
// PTX helpers (base sm_103 target: cp.async / ldmatrix / mma.sync)
// ---------------------------------------------------------------------------
__device__ __forceinline__ uint32_t smem_u32(const void* p) {
    uint32_t a;
    asm("{ .reg .u64 t; cvta.to.shared.u64 t, %1; cvt.u32.u64 %0, t; }" : "=r"(a) : "l"(p));
    return a;
}
__device__ __forceinline__ void cpasync16(uint32_t dst, const void* src) {
    asm volatile("cp.async.cg.shared.global [%0], [%1], 16;" :: "r"(dst), "l"(src));
}
#define CP_COMMIT() asm volatile("cp.async.commit_group;" ::: "memory")
#define CP_WAIT(N)  asm volatile("cp.async.wait_group %0;" :: "n"(N) : "memory")

#define LDSM4(r, addr)                                                          \
    asm volatile("ldmatrix.sync.aligned.m8n8.x4.shared.b16 {%0,%1,%2,%3}, [%4];" \
        : "=r"((r)[0]), "=r"((r)[1]), "=r"((r)[2]), "=r"((r)[3]) : "r"(addr))
#define LDSM2(r, addr)                                                          \
    asm volatile("ldmatrix.sync.aligned.m8n8.x2.shared.b16 {%0,%1}, [%2];"      \
        : "=r"((r)[0]), "=r"((r)[1]) : "r"(addr))

#define MMA_F16(c, a, b)                                                        \
    asm volatile("mma.sync.aligned.m16n8k16.row.col.f32.f16.f16.f32 "           \
        "{%0,%1,%2,%3}, {%4,%5,%6,%7}, {%8,%9}, {%0,%1,%2,%3};"                 \
        : "+f"((c)[0]), "+f"((c)[1]), "+f"((c)[2]), "+f"((c)[3])                \
        : "r"((a)[0]), "r"((a)[1]), "r"((a)[2]), "r"((a)[3]),                   \
          "r"((b)[0]), "r"((b)[1]))

// SMEM layout (dynamic):
//   [0, 2048)        : wg0/wg1/wd/bias (4 x 128 floats)
//   [4096, +4*49152) : 4 stages of [A 32K][W 16K]
constexpr int SMO_RW  = 0;
constexpr int SMO_STG = 4096;
constexpr int SZ_A  = BM * 128;              // 32768 (256 rows x 128B)
constexpr int SZ_W  = BN * 128;              // 16384
constexpr int STAGE_SZ = SZ_A + SZ_W;        // 49152
constexpr int SMEM_TOTAL = SMO_STG + 4 * STAGE_SZ;  // 200704

// ---------------------------------------------------------------------------
// pack_e: emb_full -> fp16. row r: r<64 -> emb_last[r], else emb[r-64].
// ---------------------------------------------------------------------------
__global__ void pack_e_kernel(const float* __restrict__ emb,
                              const float* __restrict__ emb_last) {
    int idx = blockIdx.x * blockDim.x + threadIdx.x;   // float2 pair index
    if (idx >= Erows * (NINP / 2)) return;
    int r = idx / (NINP / 2);
    int k = (idx - r * (NINP / 2)) * 2;
    const float* src = (r < B_) ? (emb_last + (size_t)r * NINP + k)
                                : (emb + (size_t)(r - B_) * NINP + k);
    float2 v = *(const float2*)src;
    __half2 ph; ph.x = __float2half_rn(v.x); ph.y = __float2half_rn(v.y);
    reinterpret_cast<__half2*>(g_E)[idx] = ph;
}

// ---------------------------------------------------------------------------
// pack_w: W[n][k] = conv1_w[n, i, c] * bn_scale[n]  (k = c*800 + i), fp16;
// plus reduction weights wg0/wg1/wd and folded bias.
// ---------------------------------------------------------------------------
__global__ void pack_w_kernel(const float* __restrict__ conv1_w,
                              const float* __restrict__ conv1_b,
                              const float* __restrict__ gamma,
                              const float* __restrict__ beta,
                              const float* __restrict__ mean,
                              const float* __restrict__ var,
                              const float* __restrict__ gate2_w,
                              const float* __restrict__ dist_w) {
    int idx = blockIdx.x * blockDim.x + threadIdx.x;  // pair index
    if (idx >= NP * (Ksz / 2)) return;
    int n = idx / (Ksz / 2);
    int k = (idx - n * (Ksz / 2)) * 2;
    float w0 = 0.f, w1 = 0.f;
    if (n < NHID) {
        float scale = gamma[n] * rsqrtf(var[n] + 1e-5f);
        int c = (k < NINP) ? 0 : 1;
        int i = (k < NINP) ? k : k - NINP;
        w0 = conv1_w[(size_t)n * Ksz + i * 2 + c] * scale;
        w1 = conv1_w[(size_t)n * Ksz + (i + 1) * 2 + c] * scale;
    }
    __half2 pw; pw.x = __float2half_rn(w0); pw.y = __float2half_rn(w1);
    reinterpret_cast<__half2*>(g_W)[idx] = pw;

    if (idx < NP) {
        int h = idx;
        float wg0 = 0.f, wg1 = 0.f, wd = 0.f, bz = 0.f;
        if (h < NHID) {
            if (h < 600) wg0 = gate2_w[h]; else wg1 = gate2_w[h];
            wd = dist_w[h];
            float scale = gamma[h] * rsqrtf(var[h] + 1e-5f);
            bz = (conv1_b[h] - mean[h]) * scale + beta[h];
        }
        g_rw[0 * NP + h] = wg0;
        g_rw[1 * NP + h] = wg1;
        g_rw[2 * NP + h] = wd;
        g_rw[3 * NP + h] = bz;
    }
}

// ---------------------------------------------------------------------------
// Single-product fp16 HMMA GEMM with fused reduction epilogue.
// D[m][n] = A*W (fp32 accum); v = relu(D + bias); partial dots per row.
// A[m][k]: k<800 -> E[m][k];  k>=800 -> E[m+64][k-800].
// Block: 256 threads = 8 warps (4 M x 2 N), warp tile 64x64.
// 4-buffer ring, load distance 3 (issued top-of-stage), CP_WAIT(2),
// ONE __syncthreads per stage. Dead N-pad columns skipped in last n-tile.
// ---------------------------------------------------------------------------
__global__ __launch_bounds__(256, 1)
void gemm_kernel() {
    extern __shared__ char smc[];
    const uint32_t sb = smem_u32(smc);
    const int tid  = threadIdx.x;
    const int wid  = tid >> 5;
    const int lane = tid & 31;
    const int wm   = wid & 3;
    const int wn   = wid >> 2;
    const int nt   = blockIdx.x;
    const int n0   = nt * BN;
    const int m0   = blockIdx.y * BM;

    // Last n-tile: cols >= 1200 have zero weights; skip their MMAs.
    // wn==0 covers n0+0..63 (1152..1215 -> ni<6 useful); wn==1 covers
    // 1216..1279 -> nothing useful.
    const int nilim = (nt == NT - 1) ? ((wn == 0) ? 6 : 0) : 8;

    float* sWg0  = (float*)(smc + SMO_RW);
    float* sWg1  = sWg0 + BN;
    float* sWd   = sWg1 + BN;
    float* sBias = sWd + BN;
    for (int i = tid; i < BN; i += 256) {
        sWg0[i]  = g_rw[0 * NP + n0 + i];
        sWg1[i]  = g_rw[1 * NP + n0 + i];
        sWd[i]   = g_rw[2 * NP + n0 + i];
        sBias[i] = g_rw[3 * NP + n0 + i];
    }

    // Stage loader: 3072 x 16B chunks = 12 per thread.
    auto load_stage = [&](int s, int buf) {
        const int k0 = s * BK;
        const uint32_t base = sb + SMO_STG + buf * STAGE_SZ;
#pragma unroll
        for (int i = 0; i < 12; ++i) {
            int q = tid + i * 256;
            const __half* src;
            uint32_t off;
            if (q < 2048) {                       // A: 256 rows x 8 16B-chunks
                int rr  = q >> 3;
                int cb  = q & 7;
                int k   = k0 + cb * 8;
                int row = m0 + rr + ((k < NINP) ? 0 : B_);
                int kk  = (k < NINP) ? k : (k - NINP);
                src = g_E + (size_t)row * NINP + kk;
                uint32_t o = rr * 128 + cb * 16;
                off = o ^ ((o >> 3) & 0x70);
            } else {                              // W: 128 rows x 8 chunks
                int w   = q - 2048;
                int rr  = w >> 3;
                int cb  = w & 7;
                src = g_W + (size_t)(n0 + rr) * Ksz + k0 + cb * 8;
                uint32_t o = rr * 128 + cb * 16;
                off = SZ_A + (o ^ ((o >> 3) & 0x70));
            }
            cpasync16(base + off, src);
        }
        CP_COMMIT();
    };

    float acc[4][8][4];
#pragma unroll
    for (int a = 0; a < 4; ++a)
#pragma unroll
        for (int b = 0; b < 8; ++b)
#pragma unroll
            for (int c = 0; c < 4; ++c) acc[a][b][c] = 0.f;

    load_stage(0, 0);
    load_stage(1, 1);
    load_stage(2, 2);

    for (int s = 0; s < NSTG; ++s) {
        const int buf = s & 3;
        // At this wait, exactly 2 groups are newer than stage s's group
        // (s+1, s+2 real, or dummy commits in the tail), so CP_WAIT(2)
        // guarantees stage s is resident.
        CP_WAIT(2);
        __syncthreads();   // all warps past stage s-1 -> buffer (s+3)&3 free

        if (s + 3 < NSTG) load_stage(s + 3, (s + 3) & 3);
        else CP_COMMIT();  // dummy to keep "2 newer groups" invariant

        const uint32_t aB = sb + SMO_STG + buf * STAGE_SZ;
        const uint32_t wB = aB + SZ_A;

#pragma unroll
        for (int kt = 0; kt < 4; ++kt) {
            const int kb = kt * 32;
            uint32_t af[4][4];
#pragma unroll
            for (int mi = 0; mi < 4; ++mi) {
                int row = wm * 64 + mi * 16 + (lane & 15);
                uint32_t o  = row * 128 + kb + ((lane >> 4) * 16);
                uint32_t so = o ^ ((o >> 3) & 0x70);
                LDSM4(af[mi], aB + so);
            }
            // ping-pong W fragments to overlap LDSM2 with MMAs
            uint32_t bw[2][2];
            if (nilim > 0) {
                int rowb = wn * 64 + (lane & 7);
                uint32_t ob  = rowb * 128 + kb + (((lane >> 3) & 1) * 16);
                LDSM2(bw[0], wB + (ob ^ ((ob >> 3) & 0x70)));
            }
#pragma unroll
            for (int ni = 0; ni < 8; ++ni) {
                if (ni < nilim) {
                    int cur = ni & 1;
                    if (ni + 1 < nilim) {
                        int rowb = wn * 64 + (ni + 1) * 8 + (lane & 7);
                        uint32_t ob  = rowb * 128 + kb + (((lane >> 3) & 1) * 16);
                        LDSM2(bw[cur ^ 1], wB + (ob ^ ((ob >> 3) & 0x70)));
                    }
#pragma unroll
                    for (int mi = 0; mi < 4; ++mi)
                        MMA_F16(acc[mi][ni], af[mi], bw[cur]);
                }
            }
        }
    }

    // Fused epilogue: relu(acc + bias), dot with wg0/wg1/wd, reduce per row.
    float rs[4][2][3];
#pragma unroll
    for (int mi = 0; mi < 4; ++mi)
#pragma unroll
        for (int e2 = 0; e2 < 2; ++e2)
            rs[mi][e2][0] = rs[mi][e2][1] = rs[mi][e2][2] = 0.f;

#pragma unroll
    for (int mi = 0; mi < 4; ++mi)
#pragma unroll
        for (int ni = 0; ni < 8; ++ni)
#pragma unroll
            for (int e = 0; e < 4; ++e) {
                int col = wn * 64 + ni * 8 + 2 * (lane & 3) + (e & 1);
                float v = fmaxf(acc[mi][ni][e] + sBias[col], 0.f);
                rs[mi][e >> 1][0] = fmaf(v, sWg0[col], rs[mi][e >> 1][0]);
                rs[mi][e >> 1][1] = fmaf(v, sWg1[col], rs[mi][e >> 1][1]);
                rs[mi][e >> 1][2] = fmaf(v, sWd[col],  rs[mi][e >> 1][2]);
            }

    // g_part is bt-major so the fused tail kernel reads coalesced.
    const int slot = nt * 2 + wn;
#pragma unroll
    for (int mi = 0; mi < 4; ++mi)
#pragma unroll
        for (int e2 = 0; e2 < 2; ++e2)
#pragma unroll
            for (int ch = 0; ch < 3; ++ch) {
                float v = rs[mi][e2][ch];
                v += __shfl_xor_sync(0xffffffffu, v, 1);
                v += __shfl_xor_sync(0xffffffffu, v, 2);
                if ((lane & 3) == 0) {
                    int row = m0 + wm * 64 + mi * 16 + (lane >> 2) + e2 * 8;
                    int bt  = (row & 63) * T_ + (row >> 6);
                    g_part[((size_t)ch * NSLOT + slot) * Msz + bt] = v;
                }
            }
}

// ---------------------------------------------------------------------------
// fused tail: one block per batch b. Phase 1: combine partials -> gate /
// gate_next / dist (gates cached in smem). Phase 2: mg/mgn cumprod + cum tail.
// ---------------------------------------------------------------------------
__global__ __launch_bounds__(256)
void tail_fused_kernel(const float* __restrict__ cum_gate,
                       const float* __restrict__ gate2_b,
                       const float* __restrict__ dist_b,
                       float* __restrict__ out) {
    __shared__ float sG[T_], sGn[T_];
    const int b = blockIdx.x;
    const float gb0 = gate2_b[0], gb1 = gate2_b[1], db = dist_b[0];

    for (int t = threadIdx.x; t < T_; t += 256) {
        const int bt = b * T_ + t;
        float s0 = 0.f, s1 = 0.f, sd = 0.f;
#pragma unroll
        for (int sl = 0; sl < NSLOT; ++sl) {
            s0 += g_part[(0 * NSLOT + sl) * (size_t)Msz + bt];
            s1 += g_part[(1 * NSLOT + sl) * (size_t)Msz + bt];
            sd += g_part[(2 * NSLOT + sl) * (size_t)Msz + bt];
        }
        float gate  = sigmf(s0 + gb0);
        float gaten = sigmf(s1 + gb1);
        sG[t]  = gate;
        sGn[t] = gaten;
        out[OFF_GATE + bt] = gate;
        out[OFF_DIST + bt] = sd + db;
    }
    __syncthreads();

    for (int t = threadIdx.x; t < T_; t += 256) {
        const int idx = b * T_ + t;
        float g  = sG[t];
        float gn = sGn[t];
        float pm = 1.f, pn = 1.f;
        float* om = out + OFF_MG  + (size_t)idx * NSLOTS;
        float* on = out + OFF_MGN + (size_t)idx * NSLOTS;
#pragma unroll
        for (int j = 0; j < NSLOTS; ++j) {
            int s = NSLOTS - j + t;
            float gh = (s < NSLOTS) ? cum_gate[b * NSLOTS + s] : sG[s - NSLOTS];
            pm *= sigmf((g  - gh) * 100.f + 5.f);
            pn *= sigmf((gn - gh) * 100.f + 5.f);
            om[j] = pm;
            on[j] = pn;
        }
    }
    if (threadIdx.x < NSLOTS)
        out[OFF_CUM + b * NSLOTS + threadIdx.x] = sG[T_ - NSLOTS + threadIdx.x];
}

// ---------------------------------------------------------------------------
// tail_emb: emb_full[-1] copy
// ---------------------------------------------------------------------------
__global__ void tail_emb_kernel(const float* __restrict__ emb, float* __restrict__ out) {
    int i = blockIdx.x * blockDim.x + threadIdx.x;
    if (i < B_ * NINP)
        out[OFF_EMB + i] = emb[(size_t)(T_ - 1) * B_ * NINP + i];
}

extern "C" void kernel_launch(void* const* d_in, const int* in_sizes, int n_in,
                              void* d_out, int out_size) {
    const float* emb      = (const float*)d_in[0];
    const float* emb_last = (const float*)d_in[1];
    const float* cum_gate = (const float*)d_in[2];
    const float* conv1_w  = (const float*)d_in[3];
    const float* conv1_b  = (const float*)d_in[4];
    const float* bn_gamma = (const float*)d_in[5];
    const float* bn_beta  = (const float*)d_in[6];
    const float* bn_mean  = (const float*)d_in[7];
    const float* bn_var   = (const float*)d_in[8];
    const float* gate2_w  = (const float*)d_in[9];
    const float* gate2_b  = (const float*)d_in[10];
    const float* dist_w   = (const float*)d_in[11];
    const float* dist_b   = (const float*)d_in[12];
    float* out = (float*)d_out;

    cudaFuncSetAttribute(gemm_kernel, cudaFuncAttributeMaxDynamicSharedMemorySize,
                         SMEM_TOTAL);

    pack_w_kernel<<<(NP * (Ksz / 2) + 255) / 256, 256>>>(conv1_w, conv1_b, bn_gamma,
                                                         bn_beta, bn_mean, bn_var,
                                                         gate2_w, dist_w);
    pack_e_kernel<<<(Erows * (NINP / 2) + 255) / 256, 256>>>(emb, emb_last);
    tail_emb_kernel<<<(B_ * NINP + 255) / 256, 256>>>(emb, out);
    gemm_kernel<<<dim3(NT, MT), 256, SMEM_TOTAL>>>();
    tail_fused_kernel<<<B_, 256>>>(cum_gate, gate2_b, dist_b, out);
}

// round 7
// speedup vs baseline: 1.2652x; 1.2652x over previous
#include <cuda_runtime.h>
#include <cuda_fp16.h>
#include <math.h>
#include <stdint.h>

// ---------------------------------------------------------------------------
// Problem constants
// ---------------------------------------------------------------------------
constexpr int T_     = 1024;
constexpr int B_     = 64;
constexpr int NINP   = 800;
constexpr int NHID   = 1200;
constexpr int NSLOTS = 15;

constexpr int Msz   = T_ * B_;     // 65536 rows (m = t*64 + b)
constexpr int Ksz   = 2 * NINP;    // 1600
constexpr int NP    = 1280;        // NHID padded
constexpr int Erows = Msz + B_;    // 65600 rows of emb_full flattened [t][b]

constexpr int BM = 128, BN = 128, BK = 64;
constexpr int NSTG  = Ksz / BK;    // 25
constexpr int NT    = NP / BN;     // 10
constexpr int MT    = Msz / BM;    // 512
constexpr int NSLOT = NT * 2;      // 20 partial slots

// Output layout
constexpr size_t OFF_MG   = 0;
constexpr size_t OFF_MGN  = (size_t)B_ * T_ * NSLOTS;
constexpr size_t OFF_GATE = OFF_MGN + (size_t)B_ * T_ * NSLOTS;
constexpr size_t OFF_DIST = OFF_GATE + (size_t)B_ * T_;
constexpr size_t OFF_EMB  = OFF_DIST + (size_t)B_ * T_;
constexpr size_t OFF_CUM  = OFF_EMB + (size_t)B_ * NINP;

// Scratch (device globals)
__device__ __half g_E[(size_t)Erows * NINP];    // 105 MB  fp16 emb_full
__device__ __half g_W[(size_t)NP * Ksz];        // 4.1 MB  [n][k], BN folded, fp16
__device__ float g_rw[4 * NP];                  // wg0, wg1, wd, bias
__device__ float g_part[3 * NSLOT * Msz];       // epilogue partials
__device__ float g_gate[(size_t)B_ * T_];
__device__ float g_gaten[(size_t)B_ * T_];

__device__ __forceinline__ float sigmf(float x) { return 1.f / (1.f + expf(-x)); }

// ---------------------------------------------------------------------------
// PTX helpers (base sm_103 target: cp.async / ldmatrix / mma.sync)
// ---------------------------------------------------------------------------
__device__ __forceinline__ uint32_t smem_u32(const void* p) {
    uint32_t a;
    asm("{ .reg .u64 t; cvta.to.shared.u64 t, %1; cvt.u32.u64 %0, t; }" : "=r"(a) : "l"(p));
    return a;
}
__device__ __forceinline__ void cpasync16(uint32_t dst, const void* src) {
    asm volatile("cp.async.cg.shared.global [%0], [%1], 16;" :: "r"(dst), "l"(src));
}
#define CP_COMMIT() asm volatile("cp.async.commit_group;" ::: "memory")
#define CP_WAIT(N)  asm volatile("cp.async.wait_group %0;" :: "n"(N) : "memory")

#define LDSM4(r, addr)                                                          \
    asm volatile("ldmatrix.sync.aligned.m8n8.x4.shared.b16 {%0,%1,%2,%3}, [%4];" \
        : "=r"((r)[0]), "=r"((r)[1]), "=r"((r)[2]), "=r"((r)[3]) : "r"(addr))
#define LDSM2(r, addr)                                                          \
    asm volatile("ldmatrix.sync.aligned.m8n8.x2.shared.b16 {%0,%1}, [%2];"      \
        : "=r"((r)[0]), "=r"((r)[1]) : "r"(addr))

#define MMA_F16(c, a, b)                                                        \
    asm volatile("mma.sync.aligned.m16n8k16.row.col.f32.f16.f16.f32 "           \
        "{%0,%1,%2,%3}, {%4,%5,%6,%7}, {%8,%9}, {%0,%1,%2,%3};"                 \
        : "+f"((c)[0]), "+f"((c)[1]), "+f"((c)[2]), "+f"((c)[3])                \
        : "r"((a)[0]), "r"((a)[1]), "r"((a)[2]), "r"((a)[3]),                   \
          "r"((b)[0]), "r"((b)[1]))

// SMEM layout (dynamic):
//   [0, 2048)        : wg0/wg1/wd/bias (4 x 128 floats)
//   [4096, +3*32768) : 3 stages of [A 16K][W 16K]
constexpr int SMO_RW  = 0;
constexpr int SMO_STG = 4096;
constexpr int SZ_A  = BM * 128;              // 16384 (128 rows x 128B)
constexpr int SZ_W  = BN * 128;              // 16384
constexpr int STAGE_SZ = SZ_A + SZ_W;        // 32768
constexpr int SMEM_TOTAL = SMO_STG + 3 * STAGE_SZ;  // 102400 (x2 CTAs <= 228KB)

// ---------------------------------------------------------------------------
// pack_e: emb_full -> fp16. row r: r<64 -> emb_last[r], else emb[r-64].
// ---------------------------------------------------------------------------
__global__ void pack_e_kernel(const float* __restrict__ emb,
                              const float* __restrict__ emb_last) {
    int idx = blockIdx.x * blockDim.x + threadIdx.x;   // float2 pair index
    if (idx >= Erows * (NINP / 2)) return;
    int r = idx / (NINP / 2);
    int k = (idx - r * (NINP / 2)) * 2;
    const float* src = (r < B_) ? (emb_last + (size_t)r * NINP + k)
                                : (emb + (size_t)(r - B_) * NINP + k);
    float2 v = *(const float2*)src;
    __half2 ph; ph.x = __float2half_rn(v.x); ph.y = __float2half_rn(v.y);
    reinterpret_cast<__half2*>(g_E)[idx] = ph;
}

// ---------------------------------------------------------------------------
// pack_w: W[n][k] = conv1_w[n, i, c] * bn_scale[n]  (k = c*800 + i), fp16;
// plus reduction weights wg0/wg1/wd and folded bias.
// ---------------------------------------------------------------------------
__global__ void pack_w_kernel(const float* __restrict__ conv1_w,
                              const float* __restrict__ conv1_b,
                              const float* __restrict__ gamma,
                              const float* __restrict__ beta,
                              const float* __restrict__ mean,
                              const float* __restrict__ var,
                              const float* __restrict__ gate2_w,
                              const float* __restrict__ dist_w) {
    int idx = blockIdx.x * blockDim.x + threadIdx.x;  // pair index
    if (idx >= NP * (Ksz / 2)) return;
    int n = idx / (Ksz / 2);
    int k = (idx - n * (Ksz / 2)) * 2;
    float w0 = 0.f, w1 = 0.f;
    if (n < NHID) {
        float scale = gamma[n] * rsqrtf(var[n] + 1e-5f);
        int c = (k < NINP) ? 0 : 1;
        int i = (k < NINP) ? k : k - NINP;
        w0 = conv1_w[(size_t)n * Ksz + i * 2 + c] * scale;
        w1 = conv1_w[(size_t)n * Ksz + (i + 1) * 2 + c] * scale;
    }
    __half2 pw; pw.x = __float2half_rn(w0); pw.y = __float2half_rn(w1);
    reinterpret_cast<__half2*>(g_W)[idx] = pw;

    if (idx < NP) {
        int h = idx;
        float wg0 = 0.f, wg1 = 0.f, wd = 0.f, bz = 0.f;
        if (h < NHID) {
            if (h < 600) wg0 = gate2_w[h]; else wg1 = gate2_w[h];
            wd = dist_w[h];
            float scale = gamma[h] * rsqrtf(var[h] + 1e-5f);
            bz = (conv1_b[h] - mean[h]) * scale + beta[h];
        }
        g_rw[0 * NP + h] = wg0;
        g_rw[1 * NP + h] = wg1;
        g_rw[2 * NP + h] = wd;
        g_rw[3 * NP + h] = bz;
    }
}

// ---------------------------------------------------------------------------
// Single-product fp16 HMMA GEMM with fused reduction epilogue.
// D[m][n] = A*W (fp32 accum); v = relu(D + bias); partial dots per row.
// A[m][k]: k<800 -> E[m][k];  k>=800 -> E[m+64][k-800].
// Block: 128 threads = 4 warps (2 M x 2 N), warp tile 64x64 (round-5 inner
// loop unchanged). 2 CTAs/SM so one CTA's barrier stall is hidden by the
// other CTA's MMAs. 3-buffer ring, load distance 2, loads at stage bottom,
// ONE __syncthreads per stage (identical to the round-5 schedule).
// ---------------------------------------------------------------------------
__global__ __launch_bounds__(128, 2)
void gemm_kernel() {
    extern __shared__ char smc[];
    const uint32_t sb = smem_u32(smc);
    const int tid  = threadIdx.x;
    const int wid  = tid >> 5;
    const int lane = tid & 31;
    const int wm   = wid & 1;       // warp m position (x64)
    const int wn   = wid >> 1;      // warp n position (x64)
    const int nt   = blockIdx.x;
    const int n0   = nt * BN;
    const int m0   = blockIdx.y * BM;

    float* sWg0  = (float*)(smc + SMO_RW);
    float* sWg1  = sWg0 + BN;
    float* sWd   = sWg1 + BN;
    float* sBias = sWd + BN;
    for (int i = tid; i < BN; i += 128) {
        sWg0[i]  = g_rw[0 * NP + n0 + i];
        sWg1[i]  = g_rw[1 * NP + n0 + i];
        sWd[i]   = g_rw[2 * NP + n0 + i];
        sBias[i] = g_rw[3 * NP + n0 + i];
    }

    // Stage loader: 2048 x 16B chunks = 16 per thread.
    auto load_stage = [&](int s, int buf) {
        const int k0 = s * BK;
        const uint32_t base = sb + SMO_STG + buf * STAGE_SZ;
#pragma unroll
        for (int i = 0; i < 16; ++i) {
            int q = tid + i * 128;
            const __half* src;
            uint32_t off;
            if (q < 1024) {                       // A: 128 rows x 8 16B-chunks
                int rr  = q >> 3;
                int cb  = q & 7;
                int k   = k0 + cb * 8;
                int row = m0 + rr + ((k < NINP) ? 0 : B_);
                int kk  = (k < NINP) ? k : (k - NINP);
                src = g_E + (size_t)row * NINP + kk;
                uint32_t o = rr * 128 + cb * 16;
                off = o ^ ((o >> 3) & 0x70);
            } else {                              // W: 128 rows x 8 chunks
                int w   = q - 1024;
                int rr  = w >> 3;
                int cb  = w & 7;
                src = g_W + (size_t)(n0 + rr) * Ksz + k0 + cb * 8;
                uint32_t o = rr * 128 + cb * 16;
                off = SZ_A + (o ^ ((o >> 3) & 0x70));
            }
            cpasync16(base + off, src);
        }
        CP_COMMIT();
    };

    float acc[4][8][4];
#pragma unroll
    for (int a = 0; a < 4; ++a)
#pragma unroll
        for (int b = 0; b < 8; ++b)
#pragma unroll
            for (int c = 0; c < 4; ++c) acc[a][b][c] = 0.f;

    load_stage(0, 0);
    load_stage(1, 1);

    for (int s = 0; s < NSTG; ++s) {
        const int buf = (s < 3) ? s : (s % 3);
        CP_WAIT(1);
        __syncthreads();   // stage s resident; all warps past stage s-1

        const uint32_t aB = sb + SMO_STG + buf * STAGE_SZ;
        const uint32_t wB = aB + SZ_A;

#pragma unroll
        for (int kt = 0; kt < 4; ++kt) {
            const int kb = kt * 32;
            uint32_t af[4][4];
#pragma unroll
            for (int mi = 0; mi < 4; ++mi) {
                int row = wm * 64 + mi * 16 + (lane & 15);
                uint32_t o  = row * 128 + kb + ((lane >> 4) * 16);
                uint32_t so = o ^ ((o >> 3) & 0x70);
                LDSM4(af[mi], aB + so);
            }
            // ping-pong W fragments to overlap LDSM2 with MMAs
            uint32_t bw[2][2];
            {
                int rowb = wn * 64 + 0 * 8 + (lane & 7);
                uint32_t ob  = rowb * 128 + kb + (((lane >> 3) & 1) * 16);
                LDSM2(bw[0], wB + (ob ^ ((ob >> 3) & 0x70)));
            }
#pragma unroll
            for (int ni = 0; ni < 8; ++ni) {
                int cur = ni & 1;
                if (ni < 7) {
                    int rowb = wn * 64 + (ni + 1) * 8 + (lane & 7);
                    uint32_t ob  = rowb * 128 + kb + (((lane >> 3) & 1) * 16);
                    LDSM2(bw[cur ^ 1], wB + (ob ^ ((ob >> 3) & 0x70)));
                }
#pragma unroll
                for (int mi = 0; mi < 4; ++mi) MMA_F16(acc[mi][ni], af[mi], bw[cur]);
            }
        }
        // Refill the buffer consumed at stage s-1 (all warps are past it due
        // to this stage's barrier). Load distance 2 -> buffer (s+2)%3.
        if (s + 2 < NSTG) load_stage(s + 2, (s + 2) % 3);
        else CP_COMMIT();   // keep group counts consistent for CP_WAIT(1)
    }

    // Fused epilogue: relu(acc + bias), dot with wg0/wg1/wd, reduce per row.
    float rs[4][2][3];
#pragma unroll
    for (int mi = 0; mi < 4; ++mi)
#pragma unroll
        for (int e2 = 0; e2 < 2; ++e2)
            rs[mi][e2][0] = rs[mi][e2][1] = rs[mi][e2][2] = 0.f;

#pragma unroll
    for (int mi = 0; mi < 4; ++mi)
#pragma unroll
        for (int ni = 0; ni < 8; ++ni)
#pragma unroll
            for (int e = 0; e < 4; ++e) {
                int col = wn * 64 + ni * 8 + 2 * (lane & 3) + (e & 1);
                float v = fmaxf(acc[mi][ni][e] + sBias[col], 0.f);
                rs[mi][e >> 1][0] = fmaf(v, sWg0[col], rs[mi][e >> 1][0]);
                rs[mi][e >> 1][1] = fmaf(v, sWg1[col], rs[mi][e >> 1][1]);
                rs[mi][e >> 1][2] = fmaf(v, sWd[col],  rs[mi][e >> 1][2]);
            }

    const int slot = nt * 2 + wn;
#pragma unroll
    for (int mi = 0; mi < 4; ++mi)
#pragma unroll
        for (int e2 = 0; e2 < 2; ++e2)
#pragma unroll
            for (int ch = 0; ch < 3; ++ch) {
                float v = rs[mi][e2][ch];
                v += __shfl_xor_sync(0xffffffffu, v, 1);
                v += __shfl_xor_sync(0xffffffffu, v, 2);
                if ((lane & 3) == 0) {
                    int row = m0 + wm * 64 + mi * 16 + (lane >> 2) + e2 * 8;
                    g_part[((size_t)ch * NSLOT + slot) * Msz + row] = v;
                }
            }
}

// ---------------------------------------------------------------------------
// finalize: combine partials -> gate, gate_next, distances
// ---------------------------------------------------------------------------
__global__ void finalize_kernel(const float* __restrict__ gate2_b,
                                const float* __restrict__ dist_b,
                                float* __restrict__ out) {
    int m = blockIdx.x * blockDim.x + threadIdx.x;
    if (m >= Msz) return;
    float s0 = 0.f, s1 = 0.f, sd = 0.f;
#pragma unroll
    for (int sl = 0; sl < NSLOT; ++sl) {
        s0 += g_part[(0 * NSLOT + sl) * (size_t)Msz + m];
        s1 += g_part[(1 * NSLOT + sl) * (size_t)Msz + m];
        sd += g_part[(2 * NSLOT + sl) * (size_t)Msz + m];
    }
    int t = m >> 6, b = m & 63;
    int bt = b * T_ + t;
    float gate  = sigmf(s0 + gate2_b[0]);
    float gaten = sigmf(s1 + gate2_b[1]);
    g_gate[bt]  = gate;
    g_gaten[bt] = gaten;
    out[OFF_GATE + bt] = gate;
    out[OFF_DIST + bt] = sd + dist_b[0];
}

// ---------------------------------------------------------------------------
// mg / mgn cumprod + cum[:, -15:] tail
// ---------------------------------------------------------------------------
__global__ void mg_cum_kernel(const float* __restrict__ cum_gate, float* __restrict__ out) {
    int idx = blockIdx.x * blockDim.x + threadIdx.x;
    if (idx >= B_ * T_) return;
    int b = idx >> 10, t = idx & (T_ - 1);
    float g  = g_gate[idx];
    float gn = g_gaten[idx];
    float pm = 1.f, pn = 1.f;
    float* om = out + OFF_MG  + (size_t)idx * NSLOTS;
    float* on = out + OFF_MGN + (size_t)idx * NSLOTS;
#pragma unroll
    for (int j = 0; j < NSLOTS; ++j) {
        int s = NSLOTS - j + t;
        float gh = (s < NSLOTS) ? cum_gate[b * NSLOTS + s] : g_gate[b * T_ + (s - NSLOTS)];
        pm *= sigmf((g  - gh) * 100.f + 5.f);
        pn *= sigmf((gn - gh) * 100.f + 5.f);
        om[j] = pm;
        on[j] = pn;
    }
    if (idx < B_ * NSLOTS) {
        int bb = idx / NSLOTS, j = idx % NSLOTS;
        out[OFF_CUM + idx] = g_gate[bb * T_ + (T_ - NSLOTS) + j];
    }
}

// ---------------------------------------------------------------------------
// tail_emb: emb_full[-1] copy
// ---------------------------------------------------------------------------
__global__ void tail_emb_kernel(const float* __restrict__ emb, float* __restrict__ out) {
    int i = blockIdx.x * blockDim.x + threadIdx.x;
    if (i < B_ * NINP)
        out[OFF_EMB + i] = emb[(size_t)(T_ - 1) * B_ * NINP + i];
}

extern "C" void kernel_launch(void* const* d_in, const int* in_sizes, int n_in,
                              void* d_out, int out_size) {
    const float* emb      = (const float*)d_in[0];
    const float* emb_last = (const float*)d_in[1];
    const float* cum_gate = (const float*)d_in[2];
    const float* conv1_w  = (const float*)d_in[3];
    const float* conv1_b  = (const float*)d_in[4];
    const float* bn_gamma = (const float*)d_in[5];
    const float* bn_beta  = (const float*)d_in[6];
    const float* bn_mean  = (const float*)d_in[7];
    const float* bn_var   = (const float*)d_in[8];
    const float* gate2_w  = (const float*)d_in[9];
    const float* gate2_b  = (const float*)d_in[10];
    const float* dist_w   = (const float*)d_in[11];
    const float* dist_b   = (const float*)d_in[12];
    float* out = (float*)d_out;

    cudaFuncSetAttribute(gemm_kernel, cudaFuncAttributeMaxDynamicSharedMemorySize,
                         SMEM_TOTAL);

    pack_w_kernel<<<(NP * (Ksz / 2) + 255) / 256, 256>>>(conv1_w, conv1_b, bn_gamma,
                                                         bn_beta, bn_mean, bn_var,
                                                         gate2_w, dist_w);
    pack_e_kernel<<<(Erows * (NINP / 2) + 255) / 256, 256>>>(emb, emb_last);
    tail_emb_kernel<<<(B_ * NINP + 255) / 256, 256>>>(emb, out);
    gemm_kernel<<<dim3(NT, MT), 128, SMEM_TOTAL>>>();
    finalize_kernel<<<Msz / 256, 256>>>(gate2_b, dist_b, out);
    mg_cum_kernel<<<(B_ * T_) / 256, 256>>>(cum_gate, out);
}

// round 8
// speedup vs baseline: 1.3786x; 1.0896x over previous
#include <cuda_runtime.h>
#include <cuda_fp16.h>
#include <math.h>
#include <stdint.h>

// ---------------------------------------------------------------------------
// Problem constants
// ---------------------------------------------------------------------------
constexpr int T_     = 1024;
constexpr int B_     = 64;
constexpr int NINP   = 800;
constexpr int NHID   = 1200;
constexpr int NSLOTS = 15;

constexpr int Msz   = T_ * B_;     // 65536 rows (m = t*64 + b)
constexpr int Ksz   = 2 * NINP;    // 1600
constexpr int NP    = 1280;        // NHID padded
constexpr int Erows = Msz + B_;    // 65600 rows of emb_full flattened [t][b]

constexpr int BM = 128, BN = 128, BK = 64;
constexpr int NSTG  = Ksz / BK;    // 25
constexpr int NT    = NP / BN;     // 10
constexpr int MT    = Msz / BM;    // 512
constexpr int NSLOT = NT * 2;      // 20 partial slots

// Output layout
constexpr size_t OFF_MG   = 0;
constexpr size_t OFF_MGN  = (size_t)B_ * T_ * NSLOTS;
constexpr size_t OFF_GATE = OFF_MGN + (size_t)B_ * T_ * NSLOTS;
constexpr size_t OFF_DIST = OFF_GATE + (size_t)B_ * T_;
constexpr size_t OFF_EMB  = OFF_DIST + (size_t)B_ * T_;
constexpr size_t OFF_CUM  = OFF_EMB + (size_t)B_ * NINP;

// Scratch (device globals)
__device__ __half g_E[(size_t)Erows * NINP];    // 105 MB  fp16 emb_full
__device__ __half g_W[(size_t)NP * Ksz];        // 4.1 MB  [n][k], BN folded, fp16
__device__ float g_rw[4 * NP];                  // wg0, wg1, wd, bias
__device__ float g_part[3 * NSLOT * Msz];       // epilogue partials
__device__ float g_gate[(size_t)B_ * T_];
__device__ float g_gaten[(size_t)B_ * T_];

__device__ __forceinline__ float sigmf(float x) { return 1.f / (1.f + expf(-x)); }

// ---------------------------------------------------------------------------
// PTX helpers (base sm_103 target: cp.async / ldmatrix / mma.sync)
// ---------------------------------------------------------------------------
__device__ __forceinline__ uint32_t smem_u32(const void* p) {
    uint32_t a;
    asm("{ .reg .u64 t; cvta.to.shared.u64 t, %1; cvt.u32.u64 %0, t; }" : "=r"(a) : "l"(p));
    return a;
}
__device__ __forceinline__ void cpasync16(uint32_t dst, const void* src) {
    asm volatile("cp.async.cg.shared.global [%0], [%1], 16;" :: "r"(dst), "l"(src));
}
#define CP_COMMIT() asm volatile("cp.async.commit_group;" ::: "memory")
#define CP_WAIT(N)  asm volatile("cp.async.wait_group %0;" :: "n"(N) : "memory")

#define LDSM4(r, addr)                                                          \
    asm volatile("ldmatrix.sync.aligned.m8n8.x4.shared.b16 {%0,%1,%2,%3}, [%4];" \
        : "=r"((r)[0]), "=r"((r)[1]), "=r"((r)[2]), "=r"((r)[3]) : "r"(addr))

#define MMA_F16(c, a, b0, b1)                                                   \
    asm volatile("mma.sync.aligned.m16n8k16.row.col.f32.f16.f16.f32 "           \
        "{%0,%1,%2,%3}, {%4,%5,%6,%7}, {%8,%9}, {%0,%1,%2,%3};"                 \
        : "+f"((c)[0]), "+f"((c)[1]), "+f"((c)[2]), "+f"((c)[3])                \
        : "r"((a)[0]), "r"((a)[1]), "r"((a)[2]), "r"((a)[3]),                   \
          "r"(b0), "r"(b1))

// SMEM layout (dynamic):
//   [0, 2048)        : wg0/wg1/wd/bias (4 x 128 floats)
//   [4096, +3*32768) : 3 stages of [A 16K][W 16K]
constexpr int SMO_RW  = 0;
constexpr int SMO_STG = 4096;
constexpr int SZ_A  = BM * 128;              // 16384 (128 rows x 128B)
constexpr int SZ_W  = BN * 128;              // 16384
constexpr int STAGE_SZ = SZ_A + SZ_W;        // 32768
constexpr int SMEM_TOTAL = SMO_STG + 3 * STAGE_SZ;  // 102400 (x2 CTAs <= 228KB)

// ---------------------------------------------------------------------------
// pack_e: emb_full -> fp16 (float4 loads, 16B stores).
// row r: r<64 -> emb_last[r], else emb[r-64].
// ---------------------------------------------------------------------------
__global__ void pack_e_kernel(const float* __restrict__ emb,
                              const float* __restrict__ emb_last) {
    int idx = blockIdx.x * blockDim.x + threadIdx.x;   // float4 group index
    if (idx >= Erows * (NINP / 4)) return;
    int r = idx / (NINP / 4);
    int k = (idx - r * (NINP / 4)) * 4;
    const float* src = (r < B_) ? (emb_last + (size_t)r * NINP + k)
                                : (emb + (size_t)(r - B_) * NINP + k);
    float4 v = *(const float4*)src;
    __half2 p0; p0.x = __float2half_rn(v.x); p0.y = __float2half_rn(v.y);
    __half2 p1; p1.x = __float2half_rn(v.z); p1.y = __float2half_rn(v.w);
    __half2* dst = reinterpret_cast<__half2*>(g_E) + idx * 2;
    dst[0] = p0;
    dst[1] = p1;
}

// ---------------------------------------------------------------------------
// pack_w: W[n][k] = conv1_w[n, i, c] * bn_scale[n]  (k = c*800 + i), fp16;
// plus reduction weights wg0/wg1/wd and folded bias.
// ---------------------------------------------------------------------------
__global__ void pack_w_kernel(const float* __restrict__ conv1_w,
                              const float* __restrict__ conv1_b,
                              const float* __restrict__ gamma,
                              const float* __restrict__ beta,
                              const float* __restrict__ mean,
                              const float* __restrict__ var,
                              const float* __restrict__ gate2_w,
                              const float* __restrict__ dist_w) {
    int idx = blockIdx.x * blockDim.x + threadIdx.x;  // pair index
    if (idx >= NP * (Ksz / 2)) return;
    int n = idx / (Ksz / 2);
    int k = (idx - n * (Ksz / 2)) * 2;
    float w0 = 0.f, w1 = 0.f;
    if (n < NHID) {
        float scale = gamma[n] * rsqrtf(var[n] + 1e-5f);
        int c = (k < NINP) ? 0 : 1;
        int i = (k < NINP) ? k : k - NINP;
        w0 = conv1_w[(size_t)n * Ksz + i * 2 + c] * scale;
        w1 = conv1_w[(size_t)n * Ksz + (i + 1) * 2 + c] * scale;
    }
    __half2 pw; pw.x = __float2half_rn(w0); pw.y = __float2half_rn(w1);
    reinterpret_cast<__half2*>(g_W)[idx] = pw;

    if (idx < NP) {
        int h = idx;
        float wg0 = 0.f, wg1 = 0.f, wd = 0.f, bz = 0.f;
        if (h < NHID) {
            if (h < 600) wg0 = gate2_w[h]; else wg1 = gate2_w[h];
            wd = dist_w[h];
            float scale = gamma[h] * rsqrtf(var[h] + 1e-5f);
            bz = (conv1_b[h] - mean[h]) * scale + beta[h];
        }
        g_rw[0 * NP + h] = wg0;
        g_rw[1 * NP + h] = wg1;
        g_rw[2 * NP + h] = wd;
        g_rw[3 * NP + h] = bz;
    }
}

// ---------------------------------------------------------------------------
// Templated mainloop. NILIM = number of active ni (n 8-blocks) for THIS warp,
// compile-time: 8 (full), 6 (last tile wn=0; cols>=1200 dead), 0 (last tile
// wn=1; loads+barriers only). All loop bounds constant -> no hot predication.
// W fragments: one LDSM4 per ni-PAIR (lanes 16-31 address the second block).
// ---------------------------------------------------------------------------
template<int NILIM>
__device__ __forceinline__ void run_mainloop(
    float (&acc)[4][8][4], uint32_t sb, int m0, int n0,
    int tid, int lane, int wm, int wn) {

    // Stage loader: 2048 x 16B chunks = 16 per thread (all warps).
    auto load_stage = [&](int s, int buf) {
        const int k0 = s * BK;
        const uint32_t base = sb + SMO_STG + buf * STAGE_SZ;
#pragma unroll
        for (int i = 0; i < 16; ++i) {
            int q = tid + i * 128;
            const __half* src;
            uint32_t off;
            if (q < 1024) {                       // A: 128 rows x 8 16B-chunks
                int rr  = q >> 3;
                int cb  = q & 7;
                int k   = k0 + cb * 8;
                int row = m0 + rr + ((k < NINP) ? 0 : B_);
                int kk  = (k < NINP) ? k : (k - NINP);
                src = g_E + (size_t)row * NINP + kk;
                uint32_t o = rr * 128 + cb * 16;
                off = o ^ ((o >> 3) & 0x70);
            } else {                              // W: 128 rows x 8 chunks
                int w   = q - 1024;
                int rr  = w >> 3;
                int cb  = w & 7;
                src = g_W + (size_t)(n0 + rr) * Ksz + k0 + cb * 8;
                uint32_t o = rr * 128 + cb * 16;
                off = SZ_A + (o ^ ((o >> 3) & 0x70));
            }
            cpasync16(base + off, src);
        }
        CP_COMMIT();
    };

    load_stage(0, 0);
    load_stage(1, 1);

    for (int s = 0; s < NSTG; ++s) {
        const int buf = (s < 3) ? s : (s % 3);
        CP_WAIT(1);
        __syncthreads();   // stage s resident; all warps past stage s-1

        if (NILIM > 0) {
            const uint32_t aB = sb + SMO_STG + buf * STAGE_SZ;
            const uint32_t wB = aB + SZ_A;
#pragma unroll
            for (int kt = 0; kt < 4; ++kt) {
                const int kb = kt * 32;
                uint32_t af[4][4];
#pragma unroll
                for (int mi = 0; mi < 4; ++mi) {
                    int row = wm * 64 + mi * 16 + (lane & 15);
                    uint32_t o  = row * 128 + kb + ((lane >> 4) * 16);
                    uint32_t so = o ^ ((o >> 3) & 0x70);
                    LDSM4(af[mi], aB + so);
                }
                // W: LDSM4 per ni-pair, ping-pong at pair granularity.
                // lanes 0-7: ni=2p koff0; 8-15: ni=2p koff16;
                // 16-23: ni=2p+1 koff0; 24-31: ni=2p+1 koff16.
                const int wrow = wn * 64 + ((lane >> 4) * 8) + (lane & 7);
                const int wkof = ((lane >> 3) & 1) * 16;
                uint32_t bw[2][4];
                {
                    uint32_t ob = (wrow + 0 * 16) * 128 + kb + wkof;
                    LDSM4(bw[0], wB + (ob ^ ((ob >> 3) & 0x70)));
                }
#pragma unroll
                for (int p = 0; p < NILIM / 2; ++p) {
                    int cur = p & 1;
                    if (p + 1 < NILIM / 2) {
                        uint32_t ob = (wrow + (p + 1) * 16) * 128 + kb + wkof;
                        LDSM4(bw[cur ^ 1], wB + (ob ^ ((ob >> 3) & 0x70)));
                    }
#pragma unroll
                    for (int mi = 0; mi < 4; ++mi)
                        MMA_F16(acc[mi][2 * p], af[mi], bw[cur][0], bw[cur][1]);
#pragma unroll
                    for (int mi = 0; mi < 4; ++mi)
                        MMA_F16(acc[mi][2 * p + 1], af[mi], bw[cur][2], bw[cur][3]);
                }
            }
        }
        // Refill the buffer consumed at stage s-1. Load distance 2.
        if (s + 2 < NSTG) load_stage(s + 2, (s + 2) % 3);
        else CP_COMMIT();   // keep group counts consistent for CP_WAIT(1)
    }
}

// ---------------------------------------------------------------------------
// Single-product fp16 HMMA GEMM with fused reduction epilogue.
// Block: 128 threads = 4 warps (2 M x 2 N), warp tile 64x64, 2 CTAs/SM,
// 3-buffer ring, load distance 2, ONE __syncthreads per stage.
// ---------------------------------------------------------------------------
__global__ __launch_bounds__(128, 2)
void gemm_kernel() {
    extern __shared__ char smc[];
    const uint32_t sb = smem_u32(smc);
    const int tid  = threadIdx.x;
    const int wid  = tid >> 5;
    const int lane = tid & 31;
    const int wm   = wid & 1;       // warp m position (x64)
    const int wn   = wid >> 1;      // warp n position (x64)
    const int nt   = blockIdx.x;
    const int n0   = nt * BN;
    const int m0   = blockIdx.y * BM;

    float* sWg0  = (float*)(smc + SMO_RW);
    float* sWg1  = sWg0 + BN;
    float* sWd   = sWg1 + BN;
    float* sBias = sWd + BN;
    for (int i = tid; i < BN; i += 128) {
        sWg0[i]  = g_rw[0 * NP + n0 + i];
        sWg1[i]  = g_rw[1 * NP + n0 + i];
        sWd[i]   = g_rw[2 * NP + n0 + i];
        sBias[i] = g_rw[3 * NP + n0 + i];
    }

    float acc[4][8][4];
#pragma unroll
    for (int a = 0; a < 4; ++a)
#pragma unroll
        for (int b = 0; b < 8; ++b)
#pragma unroll
            for (int c = 0; c < 4; ++c) acc[a][b][c] = 0.f;

    // Warp-uniform selection OUTSIDE the stage loop; bounds compile-time.
    if (nt != NT - 1)      run_mainloop<8>(acc, sb, m0, n0, tid, lane, wm, wn);
    else if (wn == 0)      run_mainloop<6>(acc, sb, m0, n0, tid, lane, wm, wn);
    else                   run_mainloop<0>(acc, sb, m0, n0, tid, lane, wm, wn);

    // Fused epilogue: relu(acc + bias), dot with wg0/wg1/wd, reduce per row.
    // (Skipped ni have acc=0 and zero weights/bias -> partials correct.)
    float rs[4][2][3];
#pragma unroll
    for (int mi = 0; mi < 4; ++mi)
#pragma unroll
        for (int e2 = 0; e2 < 2; ++e2)
            rs[mi][e2][0] = rs[mi][e2][1] = rs[mi][e2][2] = 0.f;

#pragma unroll
    for (int mi = 0; mi < 4; ++mi)
#pragma unroll
        for (int ni = 0; ni < 8; ++ni)
#pragma unroll
            for (int e = 0; e < 4; ++e) {
                int col = wn * 64 + ni * 8 + 2 * (lane & 3) + (e & 1);
                float v = fmaxf(acc[mi][ni][e] + sBias[col], 0.f);
                rs[mi][e >> 1][0] = fmaf(v, sWg0[col], rs[mi][e >> 1][0]);
                rs[mi][e >> 1][1] = fmaf(v, sWg1[col], rs[mi][e >> 1][1]);
                rs[mi][e >> 1][2] = fmaf(v, sWd[col],  rs[mi][e >> 1][2]);
            }

    const int slot = nt * 2 + wn;
#pragma unroll
    for (int mi = 0; mi < 4; ++mi)
#pragma unroll
        for (int e2 = 0; e2 < 2; ++e2)
#pragma unroll
            for (int ch = 0; ch < 3; ++ch) {
                float v = rs[mi][e2][ch];
                v += __shfl_xor_sync(0xffffffffu, v, 1);
                v += __shfl_xor_sync(0xffffffffu, v, 2);
                if ((lane & 3) == 0) {
                    int row = m0 + wm * 64 + mi * 16 + (lane >> 2) + e2 * 8;
                    g_part[((size_t)ch * NSLOT + slot) * Msz + row] = v;
                }
            }
}

// ---------------------------------------------------------------------------
// finalize: combine partials -> gate, gate_next, distances
// ---------------------------------------------------------------------------
__global__ void finalize_kernel(const float* __restrict__ gate2_b,
                                const float* __restrict__ dist_b,
                                float* __restrict__ out) {
    int m = blockIdx.x * blockDim.x + threadIdx.x;
    if (m >= Msz) return;
    float s0 = 0.f, s1 = 0.f, sd = 0.f;
#pragma unroll
    for (int sl = 0; sl < NSLOT; ++sl) {
        s0 += g_part[(0 * NSLOT + sl) * (size_t)Msz + m];
        s1 += g_part[(1 * NSLOT + sl) * (size_t)Msz + m];
        sd += g_part[(2 * NSLOT + sl) * (size_t)Msz + m];
    }
    int t = m >> 6, b = m & 63;
    int bt = b * T_ + t;
    float gate  = sigmf(s0 + gate2_b[0]);
    float gaten = sigmf(s1 + gate2_b[1]);
    g_gate[bt]  = gate;
    g_gaten[bt] = gaten;
    out[OFF_GATE + bt] = gate;
    out[OFF_DIST + bt] = sd + dist_b[0];
}

// ---------------------------------------------------------------------------
// mg / mgn cumprod + cum[:, -15:] tail
// ---------------------------------------------------------------------------
__global__ void mg_cum_kernel(const float* __restrict__ cum_gate, float* __restrict__ out) {
    int idx = blockIdx.x * blockDim.x + threadIdx.x;
    if (idx >= B_ * T_) return;
    int b = idx >> 10, t = idx & (T_ - 1);
    float g  = g_gate[idx];
    float gn = g_gaten[idx];
    float pm = 1.f, pn = 1.f;
    float* om = out + OFF_MG  + (size_t)idx * NSLOTS;
    float* on = out + OFF_MGN + (size_t)idx * NSLOTS;
#pragma unroll
    for (int j = 0; j < NSLOTS; ++j) {
        int s = NSLOTS - j + t;
        float gh = (s < NSLOTS) ? cum_gate[b * NSLOTS + s] : g_gate[b * T_ + (s - NSLOTS)];
        pm *= sigmf((g  - gh) * 100.f + 5.f);
        pn *= sigmf((gn - gh) * 100.f + 5.f);
        om[j] = pm;
        on[j] = pn;
    }
    if (idx < B_ * NSLOTS) {
        int bb = idx / NSLOTS, j = idx % NSLOTS;
        out[OFF_CUM + idx] = g_gate[bb * T_ + (T_ - NSLOTS) + j];
    }
}

// ---------------------------------------------------------------------------
// tail_emb: emb_full[-1] copy
// ---------------------------------------------------------------------------
__global__ void tail_emb_kernel(const float* __restrict__ emb, float* __restrict__ out) {
    int i = blockIdx.x * blockDim.x + threadIdx.x;
    if (i < B_ * NINP)
        out[OFF_EMB + i] = emb[(size_t)(T_ - 1) * B_ * NINP + i];
}

extern "C" void kernel_launch(void* const* d_in, const int* in_sizes, int n_in,
                              void* d_out, int out_size) {
    const float* emb      = (const float*)d_in[0];
    const float* emb_last = (const float*)d_in[1];
    const float* cum_gate = (const float*)d_in[2];
    const float* conv1_w  = (const float*)d_in[3];
    const float* conv1_b  = (const float*)d_in[4];
    const float* bn_gamma = (const float*)d_in[5];
    const float* bn_beta  = (const float*)d_in[6];
    const float* bn_mean  = (const float*)d_in[7];
    const float* bn_var   = (const float*)d_in[8];
    const float* gate2_w  = (const float*)d_in[9];
    const float* gate2_b  = (const float*)d_in[10];
    const float* dist_w   = (const float*)d_in[11];
    const float* dist_b   = (const float*)d_in[12];
    float* out = (float*)d_out;

    cudaFuncSetAttribute(gemm_kernel, cudaFuncAttributeMaxDynamicSharedMemorySize,
                         SMEM_TOTAL);

    pack_w_kernel<<<(NP * (Ksz / 2) + 255) / 256, 256>>>(conv1_w, conv1_b, bn_gamma,
                                                         bn_beta, bn_mean, bn_var,
                                                         gate2_w, dist_w);
    pack_e_kernel<<<(Erows * (NINP / 4) + 255) / 256, 256>>>(emb, emb_last);
    tail_emb_kernel<<<(B_ * NINP + 255) / 256, 256>>>(emb, out);
    gemm_kernel<<<dim3(NT, MT), 128, SMEM_TOTAL>>>();
    finalize_kernel<<<Msz / 256, 256>>>(gate2_b, dist_b, out);
    mg_cum_kernel<<<(B_ * T_) / 256, 256>>>(cum_gate, out);
}

// round 9
// speedup vs baseline: 1.3867x; 1.0059x over previous
#include <cuda_runtime.h>
#include <cuda_fp16.h>
#include <math.h>
#include <stdint.h>

// ---------------------------------------------------------------------------
// Problem constants
// ---------------------------------------------------------------------------
constexpr int T_     = 1024;
constexpr int B_     = 64;
constexpr int NINP   = 800;
constexpr int NHID   = 1200;
constexpr int NSLOTS = 15;

constexpr int Msz   = T_ * B_;     // 65536 rows (m = t*64 + b)
constexpr int Ksz   = 2 * NINP;    // 1600
constexpr int NP    = 1280;        // NHID padded
constexpr int Erows = Msz + B_;    // 65600 rows of emb_full flattened [t][b]

constexpr int BM = 128, BN = 128, BK = 64;
constexpr int NSTG  = Ksz / BK;    // 25
constexpr int NT    = NP / BN;     // 10
constexpr int MT    = Msz / BM;    // 512
constexpr int NSLOT = NT * 2;      // 20 partial slots

// Output layout
constexpr size_t OFF_MG   = 0;
constexpr size_t OFF_MGN  = (size_t)B_ * T_ * NSLOTS;
constexpr size_t OFF_GATE = OFF_MGN + (size_t)B_ * T_ * NSLOTS;
constexpr size_t OFF_DIST = OFF_GATE + (size_t)B_ * T_;
constexpr size_t OFF_EMB  = OFF_DIST + (size_t)B_ * T_;
constexpr size_t OFF_CUM  = OFF_EMB + (size_t)B_ * NINP;

// Scratch (device globals)
__device__ __half g_E[(size_t)Erows * NINP];    // 105 MB  fp16 emb_full
__device__ __half g_W[(size_t)NP * Ksz];        // 4.1 MB  [n][k], BN folded, fp16
__device__ float g_rw[4 * NP];                  // wg0, wg1, wd, bias
__device__ float g_part[3 * NSLOT * Msz];       // epilogue partials
__device__ float g_gate[(size_t)B_ * T_];
__device__ float g_gaten[(size_t)B_ * T_];

__device__ __forceinline__ float sigmf(float x) { return 1.f / (1.f + expf(-x)); }

// ---------------------------------------------------------------------------
// PTX helpers (base sm_103 target: cp.async / ldmatrix / mma.sync)
// ---------------------------------------------------------------------------
__device__ __forceinline__ uint32_t smem_u32(const void* p) {
    uint32_t a;
    asm("{ .reg .u64 t; cvta.to.shared.u64 t, %1; cvt.u32.u64 %0, t; }" : "=r"(a) : "l"(p));
    return a;
}
__device__ __forceinline__ void cpasync16(uint32_t dst, const void* src) {
    asm volatile("cp.async.cg.shared.global [%0], [%1], 16;" :: "r"(dst), "l"(src));
}
#define CP_COMMIT() asm volatile("cp.async.commit_group;" ::: "memory")
#define CP_WAIT(N)  asm volatile("cp.async.wait_group %0;" :: "n"(N) : "memory")

#define LDSM4(r, addr)                                                          \
    asm volatile("ldmatrix.sync.aligned.m8n8.x4.shared.b16 {%0,%1,%2,%3}, [%4];" \
        : "=r"((r)[0]), "=r"((r)[1]), "=r"((r)[2]), "=r"((r)[3]) : "r"(addr))

#define MMA_F16(c, a, b0, b1)                                                   \
    asm volatile("mma.sync.aligned.m16n8k16.row.col.f32.f16.f16.f32 "           \
        "{%0,%1,%2,%3}, {%4,%5,%6,%7}, {%8,%9}, {%0,%1,%2,%3};"                 \
        : "+f"((c)[0]), "+f"((c)[1]), "+f"((c)[2]), "+f"((c)[3])                \
        : "r"((a)[0]), "r"((a)[1]), "r"((a)[2]), "r"((a)[3]),                   \
          "r"(b0), "r"(b1))

// SMEM layout (dynamic):
//   [0, 2048)        : wg0/wg1/wd/bias (4 x 128 floats)
//   [4096, +3*32768) : 3 stages of [A 16K][W 16K]
constexpr int SMO_RW  = 0;
constexpr int SMO_STG = 4096;
constexpr int SZ_A  = BM * 128;              // 16384 (128 rows x 128B)
constexpr int SZ_W  = BN * 128;              // 16384
constexpr int STAGE_SZ = SZ_A + SZ_W;        // 32768
constexpr int SMEM_TOTAL = SMO_STG + 3 * STAGE_SZ;  // 102400 (x2 CTAs <= 228KB)

// prep_kernel block partition
constexpr int PE_BLOCKS = (Erows * (NINP / 4) + 255) / 256;  // 51250
constexpr int PW_BLOCKS = (NP * (Ksz / 2) + 255) / 256;      // 4000
constexpr int TE_BLOCKS = (B_ * NINP + 255) / 256;           // 200
constexpr int PREP_BLOCKS = PE_BLOCKS + PW_BLOCKS + TE_BLOCKS;

// ---------------------------------------------------------------------------
// prep: merged pack_e + pack_w + tail_emb (independent jobs; merging lets the
// compute-bound pack_w blocks overlap the HBM-bound pack_e stream and removes
// two kernel-boundary drains).
// ---------------------------------------------------------------------------
__global__ void prep_kernel(const float* __restrict__ emb,
                            const float* __restrict__ emb_last,
                            const float* __restrict__ conv1_w,
                            const float* __restrict__ conv1_b,
                            const float* __restrict__ gamma,
                            const float* __restrict__ beta,
                            const float* __restrict__ mean,
                            const float* __restrict__ var,
                            const float* __restrict__ gate2_w,
                            const float* __restrict__ dist_w,
                            float* __restrict__ out) {
    const int bx = blockIdx.x;
    if (bx < PE_BLOCKS) {
        // ---- pack_e: emb_full -> fp16 (float4 loads, 16B stores) ----
        int idx = bx * 256 + threadIdx.x;            // float4 group index
        if (idx >= Erows * (NINP / 4)) return;
        int r = idx / (NINP / 4);
        int k = (idx - r * (NINP / 4)) * 4;
        const float* src = (r < B_) ? (emb_last + (size_t)r * NINP + k)
                                    : (emb + (size_t)(r - B_) * NINP + k);
        float4 v = *(const float4*)src;
        __half2 p0; p0.x = __float2half_rn(v.x); p0.y = __float2half_rn(v.y);
        __half2 p1; p1.x = __float2half_rn(v.z); p1.y = __float2half_rn(v.w);
        __half2* dst = reinterpret_cast<__half2*>(g_E) + idx * 2;
        dst[0] = p0;
        dst[1] = p1;
    } else if (bx < PE_BLOCKS + PW_BLOCKS) {
        // ---- pack_w: BN-folded fp16 weights + reduction vectors ----
        int idx = (bx - PE_BLOCKS) * 256 + threadIdx.x;   // pair index
        if (idx >= NP * (Ksz / 2)) return;
        int n = idx / (Ksz / 2);
        int k = (idx - n * (Ksz / 2)) * 2;
        float w0 = 0.f, w1 = 0.f;
        if (n < NHID) {
            float scale = gamma[n] * rsqrtf(var[n] + 1e-5f);
            int c = (k < NINP) ? 0 : 1;
            int i = (k < NINP) ? k : k - NINP;
            w0 = conv1_w[(size_t)n * Ksz + i * 2 + c] * scale;
            w1 = conv1_w[(size_t)n * Ksz + (i + 1) * 2 + c] * scale;
        }
        __half2 pw; pw.x = __float2half_rn(w0); pw.y = __float2half_rn(w1);
        reinterpret_cast<__half2*>(g_W)[idx] = pw;

        if (idx < NP) {
            int h = idx;
            float wg0 = 0.f, wg1 = 0.f, wd = 0.f, bz = 0.f;
            if (h < NHID) {
                if (h < 600) wg0 = gate2_w[h]; else wg1 = gate2_w[h];
                wd = dist_w[h];
                float scale = gamma[h] * rsqrtf(var[h] + 1e-5f);
                bz = (conv1_b[h] - mean[h]) * scale + beta[h];
            }
            g_rw[0 * NP + h] = wg0;
            g_rw[1 * NP + h] = wg1;
            g_rw[2 * NP + h] = wd;
            g_rw[3 * NP + h] = bz;
        }
    } else {
        // ---- tail_emb: emb_full[-1] copy ----
        int i = (bx - PE_BLOCKS - PW_BLOCKS) * 256 + threadIdx.x;
        if (i < B_ * NINP)
            out[OFF_EMB + i] = emb[(size_t)(T_ - 1) * B_ * NINP + i];
    }
}

// ---------------------------------------------------------------------------
// Templated mainloop. NILIM = number of active ni (n 8-blocks) for THIS warp,
// compile-time: 8 (full), 6 (last tile wn=0; cols>=1200 dead), 0 (last tile
// wn=1; loads+barriers only). All loop bounds constant -> no hot predication.
// W fragments: one LDSM4 per ni-PAIR (lanes 16-31 address the second block).
// ---------------------------------------------------------------------------
template<int NILIM>
__device__ __forceinline__ void run_mainloop(
    float (&acc)[4][8][4], uint32_t sb, int m0, int n0,
    int tid, int lane, int wm, int wn) {

    // Stage loader: 2048 x 16B chunks = 16 per thread (all warps).
    auto load_stage = [&](int s, int buf) {
        const int k0 = s * BK;
        const uint32_t base = sb + SMO_STG + buf * STAGE_SZ;
#pragma unroll
        for (int i = 0; i < 16; ++i) {
            int q = tid + i * 128;
            const __half* src;
            uint32_t off;
            if (q < 1024) {                       // A: 128 rows x 8 16B-chunks
                int rr  = q >> 3;
                int cb  = q & 7;
                int k   = k0 + cb * 8;
                int row = m0 + rr + ((k < NINP) ? 0 : B_);
                int kk  = (k < NINP) ? k : (k - NINP);
                src = g_E + (size_t)row * NINP + kk;
                uint32_t o = rr * 128 + cb * 16;
                off = o ^ ((o >> 3) & 0x70);
            } else {                              // W: 128 rows x 8 chunks
                int w   = q - 1024;
                int rr  = w >> 3;
                int cb  = w & 7;
                src = g_W + (size_t)(n0 + rr) * Ksz + k0 + cb * 8;
                uint32_t o = rr * 128 + cb * 16;
                off = SZ_A + (o ^ ((o >> 3) & 0x70));
            }
            cpasync16(base + off, src);
        }
        CP_COMMIT();
    };

    load_stage(0, 0);
    load_stage(1, 1);

    for (int s = 0; s < NSTG; ++s) {
        const int buf = (s < 3) ? s : (s % 3);
        CP_WAIT(1);
        __syncthreads();   // stage s resident; all warps past stage s-1

        if (NILIM > 0) {
            const uint32_t aB = sb + SMO_STG + buf * STAGE_SZ;
            const uint32_t wB = aB + SZ_A;
#pragma unroll
            for (int kt = 0; kt < 4; ++kt) {
                const int kb = kt * 32;
                uint32_t af[4][4];
#pragma unroll
                for (int mi = 0; mi < 4; ++mi) {
                    int row = wm * 64 + mi * 16 + (lane & 15);
                    uint32_t o  = row * 128 + kb + ((lane >> 4) * 16);
                    uint32_t so = o ^ ((o >> 3) & 0x70);
                    LDSM4(af[mi], aB + so);
                }
                // W: LDSM4 per ni-pair, ping-pong at pair granularity.
                const int wrow = wn * 64 + ((lane >> 4) * 8) + (lane & 7);
                const int wkof = ((lane >> 3) & 1) * 16;
                uint32_t bw[2][4];
                {
                    uint32_t ob = (wrow + 0 * 16) * 128 + kb + wkof;
                    LDSM4(bw[0], wB + (ob ^ ((ob >> 3) & 0x70)));
                }
#pragma unroll
                for (int p = 0; p < NILIM / 2; ++p) {
                    int cur = p & 1;
                    if (p + 1 < NILIM / 2) {
                        uint32_t ob = (wrow + (p + 1) * 16) * 128 + kb + wkof;
                        LDSM4(bw[cur ^ 1], wB + (ob ^ ((ob >> 3) & 0x70)));
                    }
#pragma unroll
                    for (int mi = 0; mi < 4; ++mi)
                        MMA_F16(acc[mi][2 * p], af[mi], bw[cur][0], bw[cur][1]);
#pragma unroll
                    for (int mi = 0; mi < 4; ++mi)
                        MMA_F16(acc[mi][2 * p + 1], af[mi], bw[cur][2], bw[cur][3]);
                }
            }
        }
        // Refill the buffer consumed at stage s-1. Load distance 2.
        if (s + 2 < NSTG) load_stage(s + 2, (s + 2) % 3);
        else CP_COMMIT();   // keep group counts consistent for CP_WAIT(1)
    }
}

// ---------------------------------------------------------------------------
// Single-product fp16 HMMA GEMM with fused reduction epilogue.
// Block: 128 threads = 4 warps (2 M x 2 N), warp tile 64x64, 2 CTAs/SM,
// 3-buffer ring, load distance 2, ONE __syncthreads per stage.
// ---------------------------------------------------------------------------
__global__ __launch_bounds__(128, 2)
void gemm_kernel() {
    extern __shared__ char smc[];
    const uint32_t sb = smem_u32(smc);
    const int tid  = threadIdx.x;
    const int wid  = tid >> 5;
    const int lane = tid & 31;
    const int wm   = wid & 1;       // warp m position (x64)
    const int wn   = wid >> 1;      // warp n position (x64)
    const int nt   = blockIdx.x;
    const int n0   = nt * BN;
    const int m0   = blockIdx.y * BM;

    float* sWg0  = (float*)(smc + SMO_RW);
    float* sWg1  = sWg0 + BN;
    float* sWd   = sWg1 + BN;
    float* sBias = sWd + BN;
    for (int i = tid; i < BN; i += 128) {
        sWg0[i]  = g_rw[0 * NP + n0 + i];
        sWg1[i]  = g_rw[1 * NP + n0 + i];
        sWd[i]   = g_rw[2 * NP + n0 + i];
        sBias[i] = g_rw[3 * NP + n0 + i];
    }

    float acc[4][8][4];
#pragma unroll
    for (int a = 0; a < 4; ++a)
#pragma unroll
        for (int b = 0; b < 8; ++b)
#pragma unroll
            for (int c = 0; c < 4; ++c) acc[a][b][c] = 0.f;

    // Warp-uniform selection OUTSIDE the stage loop; bounds compile-time.
    if (nt != NT - 1)      run_mainloop<8>(acc, sb, m0, n0, tid, lane, wm, wn);
    else if (wn == 0)      run_mainloop<6>(acc, sb, m0, n0, tid, lane, wm, wn);
    else                   run_mainloop<0>(acc, sb, m0, n0, tid, lane, wm, wn);

    // Fused epilogue: relu(acc + bias), dot with wg0/wg1/wd, reduce per row.
    // (Skipped ni have acc=0 and zero weights/bias -> partials correct.)
    float rs[4][2][3];
#pragma unroll
    for (int mi = 0; mi < 4; ++mi)
#pragma unroll
        for (int e2 = 0; e2 < 2; ++e2)
            rs[mi][e2][0] = rs[mi][e2][1] = rs[mi][e2][2] = 0.f;

#pragma unroll
    for (int mi = 0; mi < 4; ++mi)
#pragma unroll
        for (int ni = 0; ni < 8; ++ni)
#pragma unroll
            for (int e = 0; e < 4; ++e) {
                int col = wn * 64 + ni * 8 + 2 * (lane & 3) + (e & 1);
                float v = fmaxf(acc[mi][ni][e] + sBias[col], 0.f);
                rs[mi][e >> 1][0] = fmaf(v, sWg0[col], rs[mi][e >> 1][0]);
                rs[mi][e >> 1][1] = fmaf(v, sWg1[col], rs[mi][e >> 1][1]);
                rs[mi][e >> 1][2] = fmaf(v, sWd[col],  rs[mi][e >> 1][2]);
            }

    const int slot = nt * 2 + wn;
#pragma unroll
    for (int mi = 0; mi < 4; ++mi)
#pragma unroll
        for (int e2 = 0; e2 < 2; ++e2)
#pragma unroll
            for (int ch = 0; ch < 3; ++ch) {
                float v = rs[mi][e2][ch];
                v += __shfl_xor_sync(0xffffffffu, v, 1);
                v += __shfl_xor_sync(0xffffffffu, v, 2);
                if ((lane & 3) == 0) {
                    int row = m0 + wm * 64 + mi * 16 + (lane >> 2) + e2 * 8;
                    g_part[((size_t)ch * NSLOT + slot) * Msz + row] = v;
                }
            }
}

// ---------------------------------------------------------------------------
// finalize: combine partials -> gate, gate_next, distances
// ---------------------------------------------------------------------------
__global__ void finalize_kernel(const float* __restrict__ gate2_b,
                                const float* __restrict__ dist_b,
                                float* __restrict__ out) {
    int m = blockIdx.x * blockDim.x + threadIdx.x;
    if (m >= Msz) return;
    float s0 = 0.f, s1 = 0.f, sd = 0.f;
#pragma unroll
    for (int sl = 0; sl < NSLOT; ++sl) {
        s0 += g_part[(0 * NSLOT + sl) * (size_t)Msz + m];
        s1 += g_part[(1 * NSLOT + sl) * (size_t)Msz + m];
        sd += g_part[(2 * NSLOT + sl) * (size_t)Msz + m];
    }
    int t = m >> 6, b = m & 63;
    int bt = b * T_ + t;
    float gate  = sigmf(s0 + gate2_b[0]);
    float gaten = sigmf(s1 + gate2_b[1]);
    g_gate[bt]  = gate;
    g_gaten[bt] = gaten;
    out[OFF_GATE + bt] = gate;
    out[OFF_DIST + bt] = sd + dist_b[0];
}

// ---------------------------------------------------------------------------
// mg / mgn cumprod + cum[:, -15:] tail
// ---------------------------------------------------------------------------
__global__ void mg_cum_kernel(const float* __restrict__ cum_gate, float* __restrict__ out) {
    int idx = blockIdx.x * blockDim.x + threadIdx.x;
    if (idx >= B_ * T_) return;
    int b = idx >> 10, t = idx & (T_ - 1);
    float g  = g_gate[idx];
    float gn = g_gaten[idx];
    float pm = 1.f, pn = 1.f;
    float* om = out + OFF_MG  + (size_t)idx * NSLOTS;
    float* on = out + OFF_MGN + (size_t)idx * NSLOTS;
#pragma unroll
    for (int j = 0; j < NSLOTS; ++j) {
        int s = NSLOTS - j + t;
        float gh = (s < NSLOTS) ? cum_gate[b * NSLOTS + s] : g_gate[b * T_ + (s - NSLOTS)];
        pm *= sigmf((g  - gh) * 100.f + 5.f);
        pn *= sigmf((gn - gh) * 100.f + 5.f);
        om[j] = pm;
        on[j] = pn;
    }
    if (idx < B_ * NSLOTS) {
        int bb = idx / NSLOTS, j = idx % NSLOTS;
        out[OFF_CUM + idx] = g_gate[bb * T_ + (T_ - NSLOTS) + j];
    }
}

extern "C" void kernel_launch(void* const* d_in, const int* in_sizes, int n_in,
                              void* d_out, int out_size) {
    const float* emb      = (const float*)d_in[0];
    const float* emb_last = (const float*)d_in[1];
    const float* cum_gate = (const float*)d_in[2];
    const float* conv1_w  = (const float*)d_in[3];
    const float* conv1_b  = (const float*)d_in[4];
    const float* bn_gamma = (const float*)d_in[5];
    const float* bn_beta  = (const float*)d_in[6];
    const float* bn_mean  = (const float*)d_in[7];
    const float* bn_var   = (const float*)d_in[8];
    const float* gate2_w  = (const float*)d_in[9];
    const float* gate2_b  = (const float*)d_in[10];
    const float* dist_w   = (const float*)d_in[11];
    const float* dist_b   = (const float*)d_in[12];
    float* out = (float*)d_out;

    cudaFuncSetAttribute(gemm_kernel, cudaFuncAttributeMaxDynamicSharedMemorySize,
                         SMEM_TOTAL);

    prep_kernel<<<PREP_BLOCKS, 256>>>(emb, emb_last, conv1_w, conv1_b, bn_gamma,
                                      bn_beta, bn_mean, bn_var, gate2_w, dist_w, out);
    gemm_kernel<<<dim3(NT, MT), 128, SMEM_TOTAL>>>();
    finalize_kernel<<<Msz / 256, 256>>>(gate2_b, dist_b, out);
    mg_cum_kernel<<<(B_ * T_) / 256, 256>>>(cum_gate, out);
}